// round 15
// baseline (speedup 1.0000x reference)
#include <cuda_runtime.h>
#include <cuda_fp16.h>

#define MAXN 50176
#define NW   12    // warps per attention block
#define KVH  68    // K/V/VT smem row stride in HALFS
#define KBS  180   // kb smem row stride in halfs
#define TBS  20    // table entry stride in halfs (40B, uint2-aligned, 16 used)

// ---------------- device scratch (no allocs allowed) ----------------
__device__ __half g_qh[MAXN * 192];
__device__ __half g_kh[MAXN * 192];
__device__ __half g_vh[MAXN * 192];
__device__ float  g_x[MAXN * 192];
__device__ int    g_minbits[3];

__device__ __forceinline__ float2 h2f(unsigned int u) {
    return __half22float2(*reinterpret_cast<__half2*>(&u));
}
__device__ __forceinline__ __half2 u2h(unsigned int u) {
    return *reinterpret_cast<__half2*>(&u);
}

// ---------------- min reduction over xyz ----------------
__global__ void init_min_kernel() {
    if (threadIdx.x < 3) g_minbits[threadIdx.x] = 0x7f7fffff;
}

__global__ void min_kernel(const float* __restrict__ xyz, int n) {
    float m0 = 1e30f, m1 = 1e30f, m2 = 1e30f;
    for (int p = blockIdx.x * blockDim.x + threadIdx.x; p < n;
         p += gridDim.x * blockDim.x) {
        m0 = fminf(m0, xyz[3 * p + 0]);
        m1 = fminf(m1, xyz[3 * p + 1]);
        m2 = fminf(m2, xyz[3 * p + 2]);
    }
#pragma unroll
    for (int s = 16; s > 0; s >>= 1) {
        m0 = fminf(m0, __shfl_xor_sync(0xffffffffu, m0, s));
        m1 = fminf(m1, __shfl_xor_sync(0xffffffffu, m1, s));
        m2 = fminf(m2, __shfl_xor_sync(0xffffffffu, m2, s));
    }
    if ((threadIdx.x & 31) == 0) {
        atomicMin(&g_minbits[0], __float_as_int(m0));
        atomicMin(&g_minbits[1], __float_as_int(m1));
        atomicMin(&g_minbits[2], __float_as_int(m2));
    }
}

// ---------------- SGEMM 256x64 tile, 8x8/thread ----------------
// split==1: write fp16 to g_qh (x0.25)/g_kh/g_vh.  split==0: fp32 C.
// A==nullptr -> read g_x.
__global__ __launch_bounds__(256) void gemm_kernel(
    const float* __restrict__ A, const float* __restrict__ B,
    const float* __restrict__ bias, float* __restrict__ C,
    int n, int N, int split)
{
    __shared__ float As[16][260];
    __shared__ float Bs[16][68];   // chunk-swizzled: chunk c at words c*4+(c>>3)*4
    const float* Ap = A ? A : g_x;
    int tid = threadIdx.x;
    int m0 = blockIdx.x * 256;
    int n0 = blockIdx.y * 64;
    int tr = tid >> 3;   // 0..31
    int tc = tid & 7;    // 0..7
    float acc[8][8];
#pragma unroll
    for (int i = 0; i < 8; i++)
#pragma unroll
        for (int j = 0; j < 8; j++) acc[i][j] = 0.f;

    for (int k0 = 0; k0 < 192; k0 += 16) {
#pragma unroll
        for (int i = 0; i < 4; i++) {
            int e = tid + i * 256;           // 1024 float4s of A slice
            int ml = e >> 2, kv = e & 3;
            int row = m0 + ml;
            float4 v = make_float4(0.f, 0.f, 0.f, 0.f);
            if (row < n) v = *(const float4*)(Ap + (size_t)row * 192 + k0 + kv * 4);
            As[kv * 4 + 0][ml] = v.x;
            As[kv * 4 + 1][ml] = v.y;
            As[kv * 4 + 2][ml] = v.z;
            As[kv * 4 + 3][ml] = v.w;
        }
        {
            int kl = tid >> 4, jv = tid & 15;
            float4 v = *(const float4*)(B + (size_t)(k0 + kl) * N + n0 + jv * 4);
            int wo = jv * 4 + (jv >> 3) * 4;   // swizzled word offset
            *(float4*)(&Bs[kl][wo]) = v;
        }
        __syncthreads();
#pragma unroll
        for (int k = 0; k < 16; k++) {
            float a[8], b[8];
            *(float4*)(a)     = *(const float4*)(&As[k][tr * 8]);
            *(float4*)(a + 4) = *(const float4*)(&As[k][tr * 8 + 4]);
            int bw = tc * 8 + (tc >> 2) * 4;
            *(float4*)(b)     = *(const float4*)(&Bs[k][bw]);
            *(float4*)(b + 4) = *(const float4*)(&Bs[k][bw + 4]);
#pragma unroll
            for (int i = 0; i < 8; i++)
#pragma unroll
                for (int j = 0; j < 8; j++) acc[i][j] += a[i] * b[j];
        }
        __syncthreads();
    }

    int col0 = n0 + tc * 8;
    if (!split) {
#pragma unroll
        for (int i = 0; i < 8; i++) {
            int row = m0 + tr * 8 + i;
            if (row >= n) continue;
            float4 o0 = make_float4(acc[i][0] + bias[col0 + 0], acc[i][1] + bias[col0 + 1],
                                    acc[i][2] + bias[col0 + 2], acc[i][3] + bias[col0 + 3]);
            float4 o1 = make_float4(acc[i][4] + bias[col0 + 4], acc[i][5] + bias[col0 + 5],
                                    acc[i][6] + bias[col0 + 6], acc[i][7] + bias[col0 + 7]);
            *(float4*)(C + (size_t)row * N + col0)     = o0;
            *(float4*)(C + (size_t)row * N + col0 + 4) = o1;
        }
    } else {
        int which = n0 / 192;                 // 64-col block lies in one tensor
        int cc0 = col0 - which * 192;
        float scl = (which == 0) ? 0.25f : 1.f;
        __half* dst = (which == 0) ? g_qh : (which == 1) ? g_kh : g_vh;
#pragma unroll
        for (int i = 0; i < 8; i++) {
            int row = m0 + tr * 8 + i;
            if (row >= n) continue;
            __half2 hx[4];
#pragma unroll
            for (int u = 0; u < 4; u++)
                hx[u] = __floats2half2_rn((acc[i][2 * u]     + bias[col0 + 2 * u])     * scl,
                                          (acc[i][2 * u + 1] + bias[col0 + 2 * u + 1]) * scl);
            *(uint4*)(dst + (size_t)row * 192 + cc0) = *(uint4*)hx;
        }
    }
}

// ---------------- fused 3-plane windowed attention ----------------
template <int NI>
__global__ __launch_bounds__(32 * NW, 2) void attn_kernel(
    const int* __restrict__ idx0, const int* __restrict__ idx1,
    const int* __restrict__ idx2,
    int M0, int M1, int M2, int Wn, int Mmax,
    const float* __restrict__ qtab, const float* __restrict__ ktab,
    const float* __restrict__ vtab, const float* __restrict__ xyz, int n)
{
    extern __shared__ float sm[];
    __half* sKh  = (__half*)sm;               // Mmax*KVH halfs
    __half* sVh  = sKh + (size_t)Mmax * KVH;  // Mmax*KVH
    __half* sVTh = sVh + (size_t)Mmax * KVH;  // 45*KVH
    __half* sKB  = sVTh + 45 * KVH;           // Mmax*KBS halfs
    __half* sQTh = sKB + (size_t)Mmax * KBS;  // 180*TBS
    __half* sKTh = sQTh + 180 * TBS;          // 180*TBS
    float*  sQB  = (float*)(sKTh + 180 * TBS);           // NW*90
    int*    sIdx = (int*)(sQB + NW * 90);     // Mmax
    int*    sQC  = sIdx + Mmax;               // Mmax
    __shared__ int sCnt;

    int b = blockIdx.x;
    int plane, w, M;
    const int* idxp;
    if (b < Wn)          { plane = 0; w = b;          M = M0; idxp = idx0; }
    else if (b < 2 * Wn) { plane = 1; w = b - Wn;     M = M1; idxp = idx1; }
    else                 { plane = 2; w = b - 2 * Wn; M = M2; idxp = idx2; }
    idxp += (size_t)w * M;

    int tid = threadIdx.x;
    const int nthr = 32 * NW;
    if (tid == 0) sCnt = M;
    for (int t = tid; t < M; t += nthr) sIdx[t] = idxp[t];
    // vt -> fp16 smem, layout [r][h*16 + d]
    for (int e = tid; e < 45 * 64; e += nthr) {
        int row = e >> 6, c = e & 63;
        int t = row / 15, l = row - t * 15;
        int hh = c >> 4, d = c & 15;
        sVTh[row * KVH + hh * 16 + d] =
            __float2half_rn(vtab[((l * 3 + t) * 4 + hh) * 16 + d]);
    }
    // q/k tables -> fp16 smem, entry idx = (t*15+l)*4 + h
    for (int e = tid; e < 180 * 16; e += nthr) {
        int idx = e >> 4, d = e & 15;
        int hh = idx & 3, tl = idx >> 2;
        int t = tl / 15, l = tl - t * 15;
        int src = ((l * 3 + t) * 4 + hh) * 16 + d;
        sQTh[idx * TBS + d] = __float2half_rn(qtab[src]);
        sKTh[idx * TBS + d] = __float2half_rn(ktab[src]);
    }
    __syncthreads();
    for (int t = tid; t < M; t += nthr)
        if (sIdx[t] >= n) atomicMin(&sCnt, t);
    __syncthreads();
    int cnt = sCnt;

    // stage K/V (already fp16 in gmem): 8 uint4 per key per tensor
    for (int e = tid; e < cnt * 8; e += nthr) {
        int j = e >> 3, q8 = e & 7;
        int p = sIdx[j];
        size_t gb = (size_t)p * 192 + plane * 64;
        uint4 kv = ((const uint4*)(g_kh + gb))[q8];
        uint4 vv = ((const uint4*)(g_vh + gb))[q8];
        uint2* kd = (uint2*)(sKh + j * KVH + q8 * 8);
        uint2* vd = (uint2*)(sVh + j * KVH + q8 * 8);
        kd[0] = make_uint2(kv.x, kv.y);
        kd[1] = make_uint2(kv.z, kv.w);
        vd[0] = make_uint2(vv.x, vv.y);
        vd[1] = make_uint2(vv.z, vv.w);
    }
    // qc computed in-kernel from xyz
    {
        float mn0 = __int_as_float(g_minbits[0]);
        float mn1 = __int_as_float(g_minbits[1]);
        float mn2 = __int_as_float(g_minbits[2]);
        const float wsA[3][3] = {{2.f, 2.f, 1.f}, {2.f, 1.f, 2.f}, {1.f, 2.f, 2.f}};
        float w0 = wsA[plane][0], w1 = wsA[plane][1], w2 = wsA[plane][2];
        for (int t = tid; t < cnt; t += nthr) {
            int p = sIdx[t];
            float vx = xyz[3 * p + 0] - mn0;
            float vy = xyz[3 * p + 1] - mn1;
            float vz = xyz[3 * p + 2] - mn2;
            int c0 = min(max((int)(fmodf(vx, w0) * 4.f), 0), (int)(w0 * 4.f) - 1);
            int c1 = min(max((int)(fmodf(vy, w1) * 4.f), 0), (int)(w1 * 4.f) - 1);
            int c2 = min(max((int)(fmodf(vz, w2) * 4.f), 0), (int)(w2 * 4.f) - 1);
            sQC[t] = c0 | (c1 << 4) | (c2 << 8);
        }
    }
    __syncthreads();

    // kb[nn, r] = sum_d K[nn,h(r),d] * ktab_s[r,d]   (HFMA2)
    for (int e = tid; e < cnt * 180; e += nthr) {
        int nn = e / 180, r = e - nn * 180;
        int hh = r & 3;
        const uint2* kp  = (const uint2*)(sKh + nn * KVH + hh * 16);
        const uint2* kt2 = (const uint2*)(sKTh + r * TBS);
        uint2 u0 = kp[0], u1 = kp[1], u2 = kp[2], u3 = kp[3];
        uint2 t0 = kt2[0], t1 = kt2[1], t2 = kt2[2], t3 = kt2[3];
        __half2 s2 = __hmul2(u2h(u0.x), u2h(t0.x));
        s2 = __hfma2(u2h(u0.y), u2h(t0.y), s2);
        s2 = __hfma2(u2h(u1.x), u2h(t1.x), s2);
        s2 = __hfma2(u2h(u1.y), u2h(t1.y), s2);
        __half2 s3 = __hmul2(u2h(u2.x), u2h(t2.x));
        s3 = __hfma2(u2h(u2.y), u2h(t2.y), s3);
        s3 = __hfma2(u2h(u3.x), u2h(t3.x), s3);
        s3 = __hfma2(u2h(u3.y), u2h(t3.y), s3);
        float2 fa = __half22float2(s2), fb = __half22float2(s3);
        sKB[nn * KBS + r] = __float2half_rn((fa.x + fa.y) + (fb.x + fb.y));
    }
    __syncthreads();

    int warp = tid >> 5, lane = tid & 31;
    float* wb = sQB + warp * 90;
    int hb = lane >> 4, ng = lane & 15;

    int nunits = 2 * cnt;
    for (int u = warp; u < nunits; u += NW) {
        int m = u >> 1, s = u & 1;
        int h = 2 * s + hb;
        int p = sIdx[m];
        __half2 q2[8];
        {
            const uint4* qg = (const uint4*)(g_qh + (size_t)p * 192 + plane * 64 + h * 16);
            uint4 qa = qg[0], qb_ = qg[1];
            q2[0] = u2h(qa.x);  q2[1] = u2h(qa.y);  q2[2] = u2h(qa.z);  q2[3] = u2h(qa.w);
            q2[4] = u2h(qb_.x); q2[5] = u2h(qb_.y); q2[6] = u2h(qb_.z); q2[7] = u2h(qb_.w);
        }
        // qb for this row's 2 heads: wb[tl*2 + hb2], table from fp16 smem
        for (int e = lane; e < 90; e += 32) {
            int tl = e >> 1, hb2 = e & 1;
            int h2i = 2 * s + hb2;
            float2 qv[8];
            if (hb2 == hb) {
#pragma unroll
                for (int d8 = 0; d8 < 8; d8++) qv[d8] = __half22float2(q2[d8]);
            } else {
                const uint4* qg2 = (const uint4*)(g_qh + (size_t)p * 192 + plane * 64 + h2i * 16);
                uint4 qa = qg2[0], qb2 = qg2[1];
                qv[0] = h2f(qa.x);  qv[1] = h2f(qa.y);  qv[2] = h2f(qa.z);  qv[3] = h2f(qa.w);
                qv[4] = h2f(qb2.x); qv[5] = h2f(qb2.y); qv[6] = h2f(qb2.z); qv[7] = h2f(qb2.w);
            }
            const uint2* qt2 = (const uint2*)(sQTh + (tl * 4 + h2i) * TBS);
            uint2 t0 = qt2[0], t1 = qt2[1], t2 = qt2[2], t3 = qt2[3];
            float2 A0 = h2f(t0.x), A1 = h2f(t0.y), B0 = h2f(t1.x), B1 = h2f(t1.y);
            float2 C0 = h2f(t2.x), C1 = h2f(t2.y), D0 = h2f(t3.x), D1 = h2f(t3.y);
            float sdot = qv[0].x * A0.x + qv[0].y * A0.y + qv[1].x * A1.x + qv[1].y * A1.y
                       + qv[2].x * B0.x + qv[2].y * B0.y + qv[3].x * B1.x + qv[3].y * B1.y
                       + qv[4].x * C0.x + qv[4].y * C0.y + qv[5].x * C1.x + qv[5].y * C1.y
                       + qv[6].x * D0.x + qv[6].y * D0.y + qv[7].x * D1.x + qv[7].y * D1.y;
            wb[e] = sdot;
        }
        __syncwarp();

        int qcm = sQC[m];
        int qm0 = (qcm & 15) + 7, qm1 = ((qcm >> 4) & 15) + 22, qm2 = ((qcm >> 8) & 15) + 37;

        // ---- phase 1: logits via HFMA2, running max; stash r packed ----
        float l[NI];
        int   rp[NI];
        float rmax = -1e30f;
#pragma unroll
        for (int i = 0; i < NI; i++) {
            int nn = ng + (i << 4);
            float dot = -1e30f;
            int rpack = 0;
            if (nn < cnt) {
                const uint2* kp = (const uint2*)(sKh + nn * KVH + (h << 4));
                uint2 u0 = kp[0], u1 = kp[1], u2 = kp[2], u3 = kp[3];
                __half2 a2 = __hmul2(q2[0], u2h(u0.x));
                a2 = __hfma2(q2[1], u2h(u0.y), a2);
                a2 = __hfma2(q2[2], u2h(u1.x), a2);
                a2 = __hfma2(q2[3], u2h(u1.y), a2);
                __half2 b2 = __hmul2(q2[4], u2h(u2.x));
                b2 = __hfma2(q2[5], u2h(u2.y), b2);
                b2 = __hfma2(q2[6], u2h(u3.x), b2);
                b2 = __hfma2(q2[7], u2h(u3.y), b2);
                float2 fa = __half22float2(a2), fb = __half22float2(b2);
                int qcn = sQC[nn];
                int r0 = qm0 - (qcn & 15);
                int r1 = qm1 - ((qcn >> 4) & 15);
                int r2 = qm2 - ((qcn >> 8) & 15);
                rpack = r0 | (r1 << 8) | (r2 << 16);
                dot = (fa.x + fa.y) + (fb.x + fb.y)
                    + wb[(r0 << 1) + hb] + __half2float(sKB[nn * KBS + (r0 << 2) + h])
                    + wb[(r1 << 1) + hb] + __half2float(sKB[nn * KBS + (r1 << 2) + h])
                    + wb[(r2 << 1) + hb] + __half2float(sKB[nn * KBS + (r2 << 2) + h]);
            }
            l[i] = dot;
            rp[i] = rpack;
            rmax = fmaxf(rmax, dot);
        }
        rmax = fmaxf(rmax, __shfl_xor_sync(0xffffffffu, rmax, 1));
        rmax = fmaxf(rmax, __shfl_xor_sync(0xffffffffu, rmax, 2));
        rmax = fmaxf(rmax, __shfl_xor_sync(0xffffffffu, rmax, 4));
        rmax = fmaxf(rmax, __shfl_xor_sync(0xffffffffu, rmax, 8));

        // ---- phase 2: exp + packed half2 V/vt accumulation ----
        float esum = 0.f;
        __half2 acc2[8];
#pragma unroll
        for (int d = 0; d < 8; d++) acc2[d] = __floats2half2_rn(0.f, 0.f);
#pragma unroll
        for (int i = 0; i < NI; i++) {
            int nn = ng + (i << 4);
            if (nn < cnt) {
                float ev = __expf(l[i] - rmax);
                esum += ev;
                __half2 ev2 = __float2half2_rn(ev);
                int r0 = rp[i] & 255, r1 = (rp[i] >> 8) & 255, r2 = (rp[i] >> 16) & 255;
                const uint2* vp  = (const uint2*)(sVh  + nn * KVH + (h << 4));
                const uint2* t0p = (const uint2*)(sVTh + r0 * KVH + (h << 4));
                const uint2* t1p = (const uint2*)(sVTh + r1 * KVH + (h << 4));
                const uint2* t2p = (const uint2*)(sVTh + r2 * KVH + (h << 4));
#pragma unroll
                for (int q = 0; q < 4; q++) {
                    uint2 uv = vp[q], w0 = t0p[q], w1 = t1p[q], w2 = t2p[q];
                    __half2 wlo = __hadd2(__hadd2(u2h(w0.x), u2h(w1.x)),
                                          __hadd2(u2h(w2.x), u2h(uv.x)));
                    __half2 whi = __hadd2(__hadd2(u2h(w0.y), u2h(w1.y)),
                                          __hadd2(u2h(w2.y), u2h(uv.y)));
                    acc2[2 * q]     = __hfma2(ev2, wlo, acc2[2 * q]);
                    acc2[2 * q + 1] = __hfma2(ev2, whi, acc2[2 * q + 1]);
                }
            }
        }

        esum += __shfl_xor_sync(0xffffffffu, esum, 1);
        esum += __shfl_xor_sync(0xffffffffu, esum, 2);
        esum += __shfl_xor_sync(0xffffffffu, esum, 4);
        esum += __shfl_xor_sync(0xffffffffu, esum, 8);
        float inv = 1.f / esum;
        float acc[16];
#pragma unroll
        for (int d = 0; d < 8; d++) {
            float2 f = __half22float2(acc2[d]);
            acc[2 * d] = f.x;
            acc[2 * d + 1] = f.y;
        }
#pragma unroll
        for (int d = 0; d < 16; d++) {
            float a = acc[d];
            a += __shfl_xor_sync(0xffffffffu, a, 1);
            a += __shfl_xor_sync(0xffffffffu, a, 2);
            a += __shfl_xor_sync(0xffffffffu, a, 4);
            a += __shfl_xor_sync(0xffffffffu, a, 8);
            acc[d] = a * inv;
        }
        if (ng == 0) {
            float4* op = (float4*)(g_x + (size_t)p * 192 + plane * 64 + h * 16);
            op[0] = make_float4(acc[0], acc[1], acc[2], acc[3]);
            op[1] = make_float4(acc[4], acc[5], acc[6], acc[7]);
            op[2] = make_float4(acc[8], acc[9], acc[10], acc[11]);
            op[3] = make_float4(acc[12], acc[13], acc[14], acc[15]);
        }
        __syncwarp();
    }
}

// ---------------- launch ----------------
extern "C" void kernel_launch(void* const* d_in, const int* in_sizes, int n_in,
                              void* d_out, int out_size) {
    const float* feats = (const float*)d_in[0];
    const float* xyz   = (const float*)d_in[1];
    const int*   idx0  = (const int*)d_in[2];
    const int*   idx1  = (const int*)d_in[3];
    const int*   idx2  = (const int*)d_in[4];
    const float* Wqkv  = (const float*)d_in[5];
    const float* bqkv  = (const float*)d_in[6];
    const float* qt    = (const float*)d_in[7];
    const float* kt    = (const float*)d_in[8];
    const float* vt    = (const float*)d_in[9];
    const float* Wp    = (const float*)d_in[10];
    const float* bp    = (const float*)d_in[11];

    int n = in_sizes[0] / 192;
    const int Wn = 1024;  // 8x8x16 grid, uniform points -> all cells occupied
    int M0 = in_sizes[2] / Wn;
    int M1 = in_sizes[3] / Wn;
    int M2 = in_sizes[4] / Wn;
    int Mmax = M0 > M1 ? M0 : M1;
    if (M2 > Mmax) Mmax = M2;

    init_min_kernel<<<1, 32>>>();
    min_kernel<<<128, 256>>>(xyz, n);

    gemm_kernel<<<dim3((n + 255) / 256, 9), 256>>>(feats, Wqkv, bqkv, nullptr, n, 576, 1);

    size_t smem = (size_t)Mmax * KVH * 2 * 2     // K,V fp16
                + (size_t)45 * KVH * 2           // VT fp16
                + (size_t)Mmax * KBS * 2         // KB fp16
                + (size_t)360 * TBS * 2          // QT+KT fp16 tables
                + (size_t)NW * 90 * 4            // per-warp qb
                + (size_t)Mmax * 8               // idx + qc
                + 64;

    int ni = (Mmax + 15) >> 4;
    if (ni <= 4) {
        cudaFuncSetAttribute(attn_kernel<4>, cudaFuncAttributeMaxDynamicSharedMemorySize, (int)smem);
        attn_kernel<4><<<3 * Wn, 32 * NW, smem>>>(idx0, idx1, idx2, M0, M1, M2, Wn, Mmax, qt, kt, vt, xyz, n);
    } else if (ni <= 5) {
        cudaFuncSetAttribute(attn_kernel<5>, cudaFuncAttributeMaxDynamicSharedMemorySize, (int)smem);
        attn_kernel<5><<<3 * Wn, 32 * NW, smem>>>(idx0, idx1, idx2, M0, M1, M2, Wn, Mmax, qt, kt, vt, xyz, n);
    } else if (ni <= 6) {
        cudaFuncSetAttribute(attn_kernel<6>, cudaFuncAttributeMaxDynamicSharedMemorySize, (int)smem);
        attn_kernel<6><<<3 * Wn, 32 * NW, smem>>>(idx0, idx1, idx2, M0, M1, M2, Wn, Mmax, qt, kt, vt, xyz, n);
    } else {
        cudaFuncSetAttribute(attn_kernel<8>, cudaFuncAttributeMaxDynamicSharedMemorySize, (int)smem);
        attn_kernel<8><<<3 * Wn, 32 * NW, smem>>>(idx0, idx1, idx2, M0, M1, M2, Wn, Mmax, qt, kt, vt, xyz, n);
    }

    gemm_kernel<<<dim3((n + 255) / 256, 3), 256>>>(nullptr, Wp, bp, (float*)d_out, n, 192, 0);
}